// round 11
// baseline (speedup 1.0000x reference)
#include <cuda_runtime.h>

#define BB 32
#define LL 64
#define NPAIRS 2016          // L*(L-1)/2
#define NUNITS 41664         // sum_{l1=1}^{62} l1*(63-l1)
#define NU4 10416            // NUNITS / 4  (exact)
#define T3BLK 41             // ceil(NU4 / 256) blocks per batch (41*256=10496)
#define KPB 41

// ---- compile-time work tables -------------------------------------------
// Order-3: unit u -> (l0,l1,l2) packed as (l0<<12)|(l1<<6)|l2, grouped so
// thread i reads one int4 = units {i, i+NU4, i+2*NU4, i+3*NU4}.
struct __align__(16) T3Tab { int v[NUNITS]; };
__host__ __device__ constexpr T3Tab make_t3() {
    T3Tab t{};
    int u = 0;
    for (int l1 = 1; l1 < 63; ++l1)
        for (int l0 = 0; l0 < l1; ++l0)
            for (int l2 = l1 + 1; l2 < 64; ++l2) {
                int i = u % NU4, k = u / NU4;
                t.v[i * 4 + k] = (l0 << 12) | (l1 << 6) | l2;
                ++u;
            }
    return t;
}
__device__ constexpr T3Tab g_t3 = make_t3();

// Order-2: pair p -> (l0<<6)|l1
struct T2Tab { int v[NPAIRS]; };
__host__ __device__ constexpr T2Tab make_t2() {
    T2Tab t{};
    int p = 0;
    for (int l1 = 1; l1 < 64; ++l1)
        for (int l0 = 0; l0 < l1; ++l0)
            t.v[p++] = (l0 << 6) | l1;
    return t;
}
__device__ constexpr T2Tab g_t2 = make_t2();

// ---- cross-block reduction scratch (zeroed at load; self-resetting) -----
__device__ float    g_acc[BB];
__device__ unsigned g_cnt[BB];

__global__ void __launch_bounds__(256) gp_kernel(
        const float* __restrict__ x,
        const float* __restrict__ th0,
        const float* __restrict__ th1,
        const float* __restrict__ th2,
        const float* __restrict__ th3,
        float* __restrict__ out) {
    const int blk = blockIdx.x;        // [0, 41) within batch
    const int b   = blockIdx.y;        // batch
    const int tid = threadIdx.x;
    const int i   = blk * 256 + tid;   // flat thread index within batch

    __shared__ int   so_s[LL];         // flattened one-hot offsets o = l*4+c
    __shared__ float wsum[8];

    if (tid < LL) {
        float4 v = ((const float4*)x)[b * LL + tid];
        int c = v.y > 0.5f ? 1 : (v.z > 0.5f ? 2 : (v.w > 0.5f ? 3 : 0));
        so_s[tid] = tid * 4 + c;
    }
    __syncthreads();

    float acc = 0.f;

    // ---- order-3: 4 table-driven gathers per thread ----
    if (i < NU4) {
        const int4 w4 = ((const int4*)g_t3.v)[i];
        const int wv[4] = {w4.x, w4.y, w4.z, w4.w};
        #pragma unroll
        for (int k = 0; k < 4; ++k) {
            const int w  = wv[k];
            const int o0 = so_s[(w >> 12) & 63];
            const int o1 = so_s[(w >> 6) & 63];
            const int o2 = so_s[w & 63];
            acc += th3[((size_t)(o0 * 256 + o1)) * 256 + o2];
        }
    }

    // ---- order-2: first 8 blocks handle one pair per thread ----
    if (blk < 8) {
        const int p = i;
        if (p < NPAIRS) {
            const int w  = g_t2.v[p];
            const int o0 = so_s[(w >> 6) & 63];
            const int o1 = so_s[w & 63];
            acc += th2[o0 * 256 + o1];
        }
    }

    // ---- order 0 + 1, folded into block 0 ----
    if (blk == 0 && tid < LL) {
        acc += th1[so_s[tid]];
        if (tid == 0) acc += th0[0];
    }

    // intra-block reduction
    #pragma unroll
    for (int off = 16; off > 0; off >>= 1)
        acc += __shfl_xor_sync(0xffffffffu, acc, off);
    const int warp = tid >> 5;
    if ((tid & 31) == 0) wsum[warp] = acc;
    __syncthreads();

    // cross-block: atomicAdd partial; last block for this batch finalizes
    if (tid == 0) {
        float t = 0.f;
        #pragma unroll
        for (int wi = 0; wi < 8; wi++) t += wsum[wi];
        atomicAdd(&g_acc[b], t);
        __threadfence();
        unsigned done = atomicAdd(&g_cnt[b], 1u);
        if (done == KPB - 1) {
            __threadfence();
            out[b] = g_acc[b];
            g_acc[b] = 0.f;      // reset for next replay
            g_cnt[b] = 0u;
        }
    }
}

extern "C" void kernel_launch(void* const* d_in, const int* in_sizes, int n_in,
                              void* d_out, int out_size) {
    const float* x   = (const float*)d_in[0];   // (B, L*C) one-hot
    const float* th0 = (const float*)d_in[1];   // (1,)
    const float* th1 = (const float*)d_in[2];   // (L, C)
    const float* th2 = (const float*)d_in[3];   // (L*C, L*C)
    const float* th3 = (const float*)d_in[4];   // (L*C, L*C, L*C)
    float* out = (float*)d_out;                 // (B, 1)

    dim3 grid(KPB, BB);
    gp_kernel<<<grid, 256>>>(x, th0, th1, th2, th3, out);
}

// round 12
// speedup vs baseline: 1.0299x; 1.0299x over previous
#include <cuda_runtime.h>

#define BB 32
#define LL 64
#define NPAIRS 2016          // L*(L-1)/2
#define CHUNKS 32            // pair-chunks; 64 pairs per chunk

// Order-2/3 pair table: p -> (l0<<6)|l1, constexpr-baked.
struct T2Tab { int v[NPAIRS]; };
__host__ __device__ constexpr T2Tab make_t2() {
    T2Tab t{};
    int p = 0;
    for (int l1 = 1; l1 < 64; ++l1)
        for (int l0 = 0; l0 < l1; ++l0)
            t.v[p++] = (l0 << 6) | l1;
    return t;
}
__device__ constexpr T2Tab g_t2 = make_t2();

// Cross-block reduction scratch (zero at module load; kernel self-resets,
// so every call — correctness, capture, each graph replay — sees zeros).
__device__ float    g_acc[BB];
__device__ unsigned g_cnt[BB];

__global__ void __launch_bounds__(256) gp_kernel(
        const float* __restrict__ x,
        const float* __restrict__ th0,
        const float* __restrict__ th1,
        const float* __restrict__ th2,
        const float* __restrict__ th3,
        float* __restrict__ out) {
    // chunk-major, batch-minor: the 32 blocks working on the SAME 64 pairs
    // (all batches) are consecutive -> co-resident -> cross-batch L2/L1 reuse
    // of theta3 rows (each pair has only 16 possible rows across batches).
    const int chunk = blockIdx.x >> 5;       // [0,32)
    const int b     = blockIdx.x & 31;       // batch
    const int tid   = threadIdx.x;
    const int sub   = tid & 3;               // lane within 4-lane group
    const int grp   = tid >> 2;              // group in block [0,64)
    const int w     = grp >> 3;              // warp [0,8)
    const int gi    = grp & 7;               // group-slot in warp [0,8)
    // balanced map: consecutive pairs within a warp (uniform trip count),
    // warps/chunks strided across the full l1 range
    const int p     = w * 256 + chunk * 8 + gi;   // [0,2048)

    __shared__ int   so_s[LL];    // flattened one-hot offsets o = l*4+c
    __shared__ float wsum[8];

    if (tid < LL) {
        float4 v = ((const float4*)x)[b * LL + tid];
        int c = v.y > 0.5f ? 1 : (v.z > 0.5f ? 2 : (v.w > 0.5f ? 3 : 0));
        so_s[tid] = tid * 4 + c;
    }
    __syncthreads();

    float acc = 0.f;

    if (p < NPAIRS) {
        const int pk = g_t2.v[p];            // table decode: no sqrt
        const int l0 = pk >> 6;
        const int l1 = pk & 63;

        const int base2 = so_s[l0] * 256 + so_s[l1];
        float t2 = (sub == 0) ? th2[base2] : 0.f;     // order-2 term

        const float* __restrict__ row = th3 + (size_t)base2 * 256;
        const int l2b = l1 + 1 + sub;

        // one-hot dot == scalar selection: row[so[l2]].
        // Fully unrolled + predicated; 4 independent accumulator chains.
        float a0 = 0.f, a1 = 0.f, a2 = 0.f, a3 = 0.f;
        #pragma unroll
        for (int t = 0; t < 4; t++) {
            int i = l2b + 4 * t;
            if (i < LL) a0 += row[so_s[i]];
        }
        #pragma unroll
        for (int t = 4; t < 8; t++) {
            int i = l2b + 4 * t;
            if (i < LL) a1 += row[so_s[i]];
        }
        #pragma unroll
        for (int t = 8; t < 12; t++) {
            int i = l2b + 4 * t;
            if (i < LL) a2 += row[so_s[i]];
        }
        #pragma unroll
        for (int t = 12; t < 16; t++) {
            int i = l2b + 4 * t;
            if (i < LL) a3 += row[so_s[i]];
        }
        acc = (a0 + a1) + (a2 + a3) + t2;
    }

    // order 0 + 1, folded into chunk-0 blocks (first 64 threads)
    if (chunk == 0 && tid < LL) {
        acc += th1[so_s[tid]];
        if (tid == 0) acc += th0[0];
    }

    // intra-block reduction
    #pragma unroll
    for (int off = 16; off > 0; off >>= 1)
        acc += __shfl_xor_sync(0xffffffffu, acc, off);
    const int warp = tid >> 5;
    if ((tid & 31) == 0) wsum[warp] = acc;
    __syncthreads();

    // cross-block: atomicAdd partial; last block for this batch finalizes
    if (tid == 0) {
        float t = 0.f;
        #pragma unroll
        for (int wi = 0; wi < 8; wi++) t += wsum[wi];
        atomicAdd(&g_acc[b], t);
        __threadfence();
        unsigned done = atomicAdd(&g_cnt[b], 1u);
        if (done == CHUNKS - 1) {
            __threadfence();
            out[b] = g_acc[b];
            g_acc[b] = 0.f;      // reset for next replay
            g_cnt[b] = 0u;
        }
    }
}

extern "C" void kernel_launch(void* const* d_in, const int* in_sizes, int n_in,
                              void* d_out, int out_size) {
    const float* x   = (const float*)d_in[0];   // (B, L*C) one-hot
    const float* th0 = (const float*)d_in[1];   // (1,)
    const float* th1 = (const float*)d_in[2];   // (L, C)
    const float* th2 = (const float*)d_in[3];   // (L*C, L*C)
    const float* th3 = (const float*)d_in[4];   // (L*C, L*C, L*C)
    float* out = (float*)d_out;                 // (B, 1)

    gp_kernel<<<BB * CHUNKS, 256>>>(x, th0, th1, th2, th3, out);
}